// round 8
// baseline (speedup 1.0000x reference)
#include <cuda_runtime.h>
#include <cuda_fp16.h>
#include <cstdint>
#include <cstddef>

#define B_   512
#define IN_  4096
#define OUT_ 11008

#define MT      256
#define NT      64
#define NTILES  172          // OUT / NT
#define KSPLIT  4
#define KPART   1024         // IN / KSPLIT
#define BK      64
#define NCH     16           // KPART / BK
#define AS      72           // smem row stride in halves (64 + 8 pad)
#define PLANE   ((size_t)B_ * OUT_)

// static device scratch (no runtime allocation)
__device__ __align__(1024) __half g_x[(size_t)B_ * IN_];
__device__ __align__(1024) float  g_part[KSPLIT * PLANE];   // 90 MB partials

// ---------------- helpers ----------------------------------------------------
__device__ __forceinline__ uint32_t smem_u32(const void* p) {
    uint32_t a;
    asm("{ .reg .u64 t; cvta.to.shared.u64 t, %1; cvt.u32.u64 %0, t; }"
        : "=r"(a) : "l"(p));
    return a;
}
#define CP16(dst, src) \
    asm volatile("cp.async.cg.shared.global [%0], [%1], 16;" :: "r"(dst), "l"(src))
#define CP_COMMIT() asm volatile("cp.async.commit_group;" ::: "memory")

__device__ __forceinline__ void ldsm_x4(uint32_t* r, uint32_t addr) {
    asm volatile("ldmatrix.sync.aligned.m8n8.x4.shared.b16 {%0,%1,%2,%3}, [%4];"
                 : "=r"(r[0]), "=r"(r[1]), "=r"(r[2]), "=r"(r[3]) : "r"(addr));
}
__device__ __forceinline__ void mma16816(float* c, const uint32_t* a, const uint32_t* b) {
    asm volatile(
        "mma.sync.aligned.m16n8k16.row.col.f32.f16.f16.f32 "
        "{%0,%1,%2,%3}, {%4,%5,%6,%7}, {%8,%9}, {%0,%1,%2,%3};\n"
        : "+f"(c[0]), "+f"(c[1]), "+f"(c[2]), "+f"(c[3])
        : "r"(a[0]), "r"(a[1]), "r"(a[2]), "r"(a[3]), "r"(b[0]), "r"(b[1]));
}

// ---------------- kernel 1: x fp32 -> fp16 -----------------------------------
__global__ void xconv_kernel(const float* __restrict__ x) {
    const int n4 = (B_ * IN_) / 4;
    int stride = gridDim.x * blockDim.x;
    for (int i = blockIdx.x * blockDim.x + threadIdx.x; i < n4; i += stride) {
        float4 v = reinterpret_cast<const float4*>(x)[i];
        __half2 lo = __floats2half2_rn(v.x, v.y);
        __half2 hi = __floats2half2_rn(v.z, v.w);
        uint2 o;
        o.x = *reinterpret_cast<uint32_t*>(&lo);
        o.y = *reinterpret_cast<uint32_t*>(&hi);
        reinterpret_cast<uint2*>(g_x)[i] = o;
    }
}

// ---------------- fused dequant + GEMM kernel --------------------------------
// Tile: M=256 (half batch), N=64, K=1024 (quarter). Grid = 172 x 4 x 2.
// bid = ((kq*NTILES + ntile)*2 + mhalf)  -> mhalf pair adjacent for L2 reuse.
static constexpr uint32_t ASZ_B = MT * AS * 2;           // 36864
static constexpr uint32_t BSZ_B = NT * AS * 2;           // 9216
static constexpr uint32_t SMEM_REQ = 2 * ASZ_B + 2 * BSZ_B + 2048;  // 94208

__global__ void __launch_bounds__(256, 2)
fused_kernel(const int* __restrict__ stored, const int* __restrict__ sign,
             const float* __restrict__ lmin_p, const float* __restrict__ lmax_p) {
    extern __shared__ char smem[];
    const uint32_t sA0 = smem_u32(smem);
    const uint32_t sB0 = sA0 + 2 * ASZ_B;
    unsigned* lut = reinterpret_cast<unsigned*>(smem + 2 * ASZ_B + 2 * BSZ_B);

    const int tid  = threadIdx.x;
    const int wid  = tid >> 5;
    const int lane = tid & 31;
    const int mhalf = blockIdx.x & 1;
    const int u     = blockIdx.x >> 1;
    const int ntile = u % NTILES;
    const int kq    = u / NTILES;
    const int n0    = ntile * NT;
    const int k0    = kq * KPART;
    const int m0    = mhalf * MT;

    // ---- build LUT ----
    {
        float lmin = __ldg(lmin_p);
        float lmax = __ldg(lmax_p);
        for (int i = tid; i < 511; i += 256) {
            int s = i - 255;
            int mag = s < 0 ? -s : s;
            float w = 0.0f;
            if (s != 0) {
                float nrm = (255.0f - (float)mag) * (1.0f / 254.0f);
                w = expf(lmin + nrm * (lmax - lmin));
                if (s < 0) w = -w;
            }
            unsigned hb = (unsigned)__half_as_ushort(__float2half_rn(w));
            lut[i] = hb | (hb << 16);
        }
    }
    __syncthreads();

    // ---- A fill geometry: 8 x 16B per thread per chunk ----
    int arow[8], acol[8];
    uint32_t adst[2][8];
#pragma unroll
    for (int j = 0; j < 8; j++) {
        int idx = j * 256 + tid;          // 0..2047
        arow[j] = idx >> 3;               // 0..255
        acol[j] = (idx & 7) * 8;          // halves
#pragma unroll
        for (int s = 0; s < 2; s++)
            adst[s][j] = sA0 + s * ASZ_B + (uint32_t)(arow[j] * AS + acol[j]) * 2;
    }
    auto fillA = [&](int chunk, int s) {
        const __half* base = g_x + (size_t)m0 * IN_ + k0 + chunk * BK;
#pragma unroll
        for (int j = 0; j < 8; j++)
            CP16(adst[s][j], base + (size_t)arow[j] * IN_ + acol[j]);
        CP_COMMIT();
    };

    // ---- B dequant: 16 elems per thread per chunk (64x64 tile / 256 thr) ----
    const int drow = tid >> 2;            // 0..63
    const int dkq  = (tid & 3) * 16;      // k offset within chunk
    const int* stp = stored + (size_t)(n0 + drow) * IN_ + k0 + dkq;
    const int* sgp = sign   + (size_t)(n0 + drow) * IN_ + k0 + dkq;
    uint32_t bdst[2];
#pragma unroll
    for (int s = 0; s < 2; s++)
        bdst[s] = sB0 + s * BSZ_B + (uint32_t)(drow * AS + dkq) * 2;

    auto stsB = [&](int chunk, int s) {
        const int4* a = reinterpret_cast<const int4*>(stp + chunk * BK);
        const int4* b = reinterpret_cast<const int4*>(sgp + chunk * BK);
#pragma unroll
        for (int h = 0; h < 2; h++) {
            int4 s0 = a[2 * h], s1 = a[2 * h + 1];
            int4 g0 = b[2 * h], g1 = b[2 * h + 1];
            unsigned l0 = lut[g0.x * s0.x + 255];
            unsigned l1 = lut[g0.y * s0.y + 255];
            unsigned l2 = lut[g0.z * s0.z + 255];
            unsigned l3 = lut[g0.w * s0.w + 255];
            unsigned l4 = lut[g1.x * s1.x + 255];
            unsigned l5 = lut[g1.y * s1.y + 255];
            unsigned l6 = lut[g1.z * s1.z + 255];
            unsigned l7 = lut[g1.w * s1.w + 255];
            uint32_t w0 = __byte_perm(l0, l1, 0x5410);
            uint32_t w1 = __byte_perm(l2, l3, 0x5410);
            uint32_t w2 = __byte_perm(l4, l5, 0x5410);
            uint32_t w3 = __byte_perm(l6, l7, 0x5410);
            asm volatile("st.shared.v4.b32 [%0], {%1,%2,%3,%4};"
                         :: "r"(bdst[s] + h * 16), "r"(w0), "r"(w1), "r"(w2), "r"(w3)
                         : "memory");
        }
    };

    // ---- ldmatrix offsets (8 warps: wm 0..3 x 64 rows, wn 0..1 x 32 cols) ---
    const int wm = wid >> 1;
    const int wn = wid & 1;
    const int lr = lane & 7;
    const int lj = lane >> 3;
    uint32_t aOff[4][4], bOff[4][2];
#pragma unroll
    for (int ks = 0; ks < 4; ks++) {
        int kk = ks * 16;
#pragma unroll
        for (int mf = 0; mf < 4; mf++) {
            int row = wm * 64 + mf * 16 + lr + (lj & 1) * 8;
            int col = kk + (lj >> 1) * 8;
            aOff[ks][mf] = (uint32_t)(row * AS + col) * 2;
        }
#pragma unroll
        for (int nh = 0; nh < 2; nh++) {
            int nrow = wn * 32 + nh * 16 + lr + (lj >> 1) * 8;
            int col  = kk + (lj & 1) * 8;
            bOff[ks][nh] = (uint32_t)(nrow * AS + col) * 2;
        }
    }

    float acc[4][4][4];
#pragma unroll
    for (int a = 0; a < 4; a++)
#pragma unroll
        for (int b = 0; b < 4; b++)
#pragma unroll
            for (int q = 0; q < 4; q++) acc[a][b][q] = 0.0f;

    // ---- prologue ----
    stsB(0, 0);
    fillA(0, 0);
    stsB(1, 1);
    fillA(1, 1);

    // ---- main loop ----
    for (int i = 0; i < NCH; i++) {
        const int s = i & 1;
        if (i < NCH - 1) asm volatile("cp.async.wait_group 1;" ::: "memory");
        else             asm volatile("cp.async.wait_group 0;" ::: "memory");
        __syncthreads();                       // A(s) + B(s) visible

        uint32_t aBase = sA0 + s * ASZ_B;
        uint32_t bBase = sB0 + s * BSZ_B;
#pragma unroll
        for (int ks = 0; ks < 4; ks++) {
            uint32_t a_frag[4][4];
            uint32_t b_frag[4][2];
#pragma unroll
            for (int mf = 0; mf < 4; mf++)
                ldsm_x4(a_frag[mf], aBase + aOff[ks][mf]);
#pragma unroll
            for (int nh = 0; nh < 2; nh++) {
                uint32_t r[4];
                ldsm_x4(r, bBase + bOff[ks][nh]);
                b_frag[2 * nh][0]     = r[0];
                b_frag[2 * nh][1]     = r[1];
                b_frag[2 * nh + 1][0] = r[2];
                b_frag[2 * nh + 1][1] = r[3];
            }
#pragma unroll
            for (int mf = 0; mf < 4; mf++)
#pragma unroll
                for (int nf = 0; nf < 4; nf++)
                    mma16816(acc[mf][nf], a_frag[mf], b_frag[nf]);
        }

        __syncthreads();                       // stage s free for refill
        if (i + 2 < NCH) {
            stsB(i + 2, s);                    // B(i+2) -> stage s
            fillA(i + 2, s);                   // A(i+2) -> stage s
        }
    }

    // ---- epilogue: plain float2 stores into the partial plane ----
    float* plane = g_part + (size_t)kq * PLANE;
    const int lq = lane >> 2;
    const int lp = lane & 3;
#pragma unroll
    for (int mf = 0; mf < 4; mf++) {
        int grow = m0 + wm * 64 + mf * 16 + lq;
#pragma unroll
        for (int nf = 0; nf < 4; nf++) {
            int gcol = n0 + wn * 32 + nf * 8 + 2 * lp;
            float* p = plane + (size_t)grow * OUT_ + gcol;
            float2 v0, v1;
            v0.x = acc[mf][nf][0];
            v0.y = acc[mf][nf][1];
            v1.x = acc[mf][nf][2];
            v1.y = acc[mf][nf][3];
            *reinterpret_cast<float2*>(p)            = v0;
            *reinterpret_cast<float2*>(p + 8 * OUT_) = v1;
        }
    }
}

// ---------------- reduce kernel: out = (sum(partials) + bias) * scale --------
__global__ void reduce_kernel(const float* __restrict__ bias,
                              const float* __restrict__ scale,
                              float* __restrict__ out) {
    const int n4 = (int)(PLANE / 4);
    int stride = gridDim.x * blockDim.x;
    for (int i = blockIdx.x * blockDim.x + threadIdx.x; i < n4; i += stride) {
        size_t e = (size_t)i * 4;
        int col = (int)(e % OUT_);
        float4 p0 = __ldg(reinterpret_cast<const float4*>(g_part + e));
        float4 p1 = __ldg(reinterpret_cast<const float4*>(g_part + PLANE + e));
        float4 p2 = __ldg(reinterpret_cast<const float4*>(g_part + 2 * PLANE + e));
        float4 p3 = __ldg(reinterpret_cast<const float4*>(g_part + 3 * PLANE + e));
        float4 b  = __ldg(reinterpret_cast<const float4*>(bias + col));
        float4 c  = __ldg(reinterpret_cast<const float4*>(scale + col));
        float4 r;
        r.x = (p0.x + p1.x + p2.x + p3.x + b.x) * c.x;
        r.y = (p0.y + p1.y + p2.y + p3.y + b.y) * c.y;
        r.z = (p0.z + p1.z + p2.z + p3.z + b.z) * c.z;
        r.w = (p0.w + p1.w + p2.w + p3.w + b.w) * c.w;
        reinterpret_cast<float4*>(out)[i] = r;
    }
}

// ---------------- launch -----------------------------------------------------
extern "C" void kernel_launch(void* const* d_in, const int* in_sizes, int n_in,
                              void* d_out, int out_size) {
    const float* x      = (const float*)d_in[0];
    const int*   stored = (const int*)d_in[1];
    const int*   sign   = (const int*)d_in[2];
    const float* lmin   = (const float*)d_in[3];
    const float* lmax   = (const float*)d_in[4];
    const float* scale  = (const float*)d_in[5];
    const float* bias   = (const float*)d_in[6];
    float* out = (float*)d_out;

    cudaFuncSetAttribute(fused_kernel, cudaFuncAttributeMaxDynamicSharedMemorySize,
                         (int)SMEM_REQ);

    xconv_kernel<<<1024, 256>>>(x);
    fused_kernel<<<NTILES * KSPLIT * 2, 256, SMEM_REQ>>>(stored, sign, lmin, lmax);
    reduce_kernel<<<1024, 256>>>(bias, scale, out);
}

// round 9
// speedup vs baseline: 1.3655x; 1.3655x over previous
#include <cuda_runtime.h>
#include <cuda_fp16.h>
#include <cstdint>
#include <cstddef>

#define B_   512
#define IN_  4096
#define OUT_ 11008

#define MT      512
#define NT      64
#define NTILES  172          // OUT / NT
#define KSPLIT  4
#define KPART   1024         // IN / KSPLIT
#define BK      64
#define NCH     16           // KPART / BK
#define PLANE   ((size_t)B_ * OUT_)

// static device scratch (no runtime allocation)
__device__ __align__(1024) __half g_x[(size_t)B_ * IN_];
__device__ __align__(1024) float  g_part[KSPLIT * PLANE];   // 90 MB partials

// ---------------- helpers ----------------------------------------------------
__device__ __forceinline__ uint32_t smem_u32(const void* p) {
    uint32_t a;
    asm("{ .reg .u64 t; cvta.to.shared.u64 t, %1; cvt.u32.u64 %0, t; }"
        : "=r"(a) : "l"(p));
    return a;
}
#define CP16(dst, src) \
    asm volatile("cp.async.cg.shared.global [%0], [%1], 16;" :: "r"(dst), "l"(src))
#define CP_COMMIT() asm volatile("cp.async.commit_group;" ::: "memory")

__device__ __forceinline__ void ldsm_x4(uint32_t* r, uint32_t addr) {
    asm volatile("ldmatrix.sync.aligned.m8n8.x4.shared.b16 {%0,%1,%2,%3}, [%4];"
                 : "=r"(r[0]), "=r"(r[1]), "=r"(r[2]), "=r"(r[3]) : "r"(addr));
}
__device__ __forceinline__ void mma16816(float* c, const uint32_t* a, const uint32_t* b) {
    asm volatile(
        "mma.sync.aligned.m16n8k16.row.col.f32.f16.f16.f32 "
        "{%0,%1,%2,%3}, {%4,%5,%6,%7}, {%8,%9}, {%0,%1,%2,%3};\n"
        : "+f"(c[0]), "+f"(c[1]), "+f"(c[2]), "+f"(c[3])
        : "r"(a[0]), "r"(a[1]), "r"(a[2]), "r"(a[3]), "r"(b[0]), "r"(b[1]));
}

// ---------------- kernel 1: x fp32 -> fp16 -----------------------------------
__global__ void xconv_kernel(const float* __restrict__ x) {
    const int n4 = (B_ * IN_) / 4;
    int stride = gridDim.x * blockDim.x;
    for (int i = blockIdx.x * blockDim.x + threadIdx.x; i < n4; i += stride) {
        float4 v = reinterpret_cast<const float4*>(x)[i];
        __half2 lo = __floats2half2_rn(v.x, v.y);
        __half2 hi = __floats2half2_rn(v.z, v.w);
        uint2 o;
        o.x = *reinterpret_cast<uint32_t*>(&lo);
        o.y = *reinterpret_cast<uint32_t*>(&hi);
        reinterpret_cast<uint2*>(g_x)[i] = o;
    }
}

// ---------------- fused dequant + GEMM kernel --------------------------------
// Tile: M=512, N=64, K=1024. Grid = 172 x 4. 3-stage XOR-swizzled smem pipe.
// Swizzle: 128B rows, 16B chunk c16' = c16 ^ (row & 7).
static constexpr uint32_t ASZ = MT * 128;            // 65536 per stage
static constexpr uint32_t BSZ = NT * 128;            // 8192 per stage
static constexpr uint32_t SMEM_REQ = 3 * ASZ + 3 * BSZ + 2048;  // 223232

__global__ void __launch_bounds__(512, 1)
fused_kernel(const int* __restrict__ stored, const int* __restrict__ sign,
             const float* __restrict__ lmin_p, const float* __restrict__ lmax_p) {
    extern __shared__ char smem[];
    const uint32_t sA0 = smem_u32(smem);
    const uint32_t sB0 = sA0 + 3 * ASZ;
    unsigned* lut = reinterpret_cast<unsigned*>(smem + 3 * ASZ + 3 * BSZ);

    const int tid  = threadIdx.x;
    const int wid  = tid >> 5;
    const int lane = tid & 31;
    const int ntile = blockIdx.x % NTILES;
    const int kq    = blockIdx.x / NTILES;
    const int n0    = ntile * NT;
    const int k0    = kq * KPART;

    // ---- build LUT ----
    {
        float lmin = __ldg(lmin_p);
        float lmax = __ldg(lmax_p);
        if (tid < 511) {
            int s = tid - 255;
            int mag = s < 0 ? -s : s;
            float w = 0.0f;
            if (s != 0) {
                float nrm = (255.0f - (float)mag) * (1.0f / 254.0f);
                w = expf(lmin + nrm * (lmax - lmin));
                if (s < 0) w = -w;
            }
            unsigned hb = (unsigned)__half_as_ushort(__float2half_rn(w));
            lut[tid] = hb | (hb << 16);
        }
    }
    __syncthreads();

    // ---- A fill geometry: 8 x 16B chunks per thread, swizzled ----
    int arow[8];
    uint32_t adoff[8];   // byte offset within a stage (swizzled)
    int asrc[8];         // half offset within a row-chunk
#pragma unroll
    for (int j = 0; j < 8; j++) {
        int idx = j * 512 + tid;          // 0..4095
        int row = idx >> 3;               // 0..511
        int c16 = idx & 7;
        arow[j] = row;
        asrc[j] = c16 * 8;
        adoff[j] = (uint32_t)(row * 128 + ((c16 ^ (row & 7)) << 4));
    }
    auto fillA = [&](int chunk, uint32_t aStage) {
        const __half* base = g_x + k0 + chunk * BK;
#pragma unroll
        for (int j = 0; j < 8; j++)
            CP16(aStage + adoff[j], base + (size_t)arow[j] * IN_ + asrc[j]);
        CP_COMMIT();
    };

    // ---- B dequant: 8 elems (one 16B chunk) per thread ----
    const int drow = tid >> 3;            // 0..63
    const int dc16 = tid & 7;
    const int* stp = stored + (size_t)(n0 + drow) * IN_ + k0 + dc16 * 8;
    const int* sgp = sign   + (size_t)(n0 + drow) * IN_ + k0 + dc16 * 8;
    const uint32_t bdoff = (uint32_t)(drow * 128 + ((dc16 ^ (drow & 7)) << 4));

    int4 st0, st1, sg0, sg1;
    auto bLDG = [&](int chunk) {
        const int4* a = reinterpret_cast<const int4*>(stp + chunk * BK);
        const int4* b = reinterpret_cast<const int4*>(sgp + chunk * BK);
        st0 = a[0]; st1 = a[1];
        sg0 = b[0]; sg1 = b[1];
    };
    auto bSTS = [&](uint32_t bStage) {
        unsigned l0 = lut[sg0.x * st0.x + 255];
        unsigned l1 = lut[sg0.y * st0.y + 255];
        unsigned l2 = lut[sg0.z * st0.z + 255];
        unsigned l3 = lut[sg0.w * st0.w + 255];
        unsigned l4 = lut[sg1.x * st1.x + 255];
        unsigned l5 = lut[sg1.y * st1.y + 255];
        unsigned l6 = lut[sg1.z * st1.z + 255];
        unsigned l7 = lut[sg1.w * st1.w + 255];
        uint32_t w0 = __byte_perm(l0, l1, 0x5410);
        uint32_t w1 = __byte_perm(l2, l3, 0x5410);
        uint32_t w2 = __byte_perm(l4, l5, 0x5410);
        uint32_t w3 = __byte_perm(l6, l7, 0x5410);
        asm volatile("st.shared.v4.b32 [%0], {%1,%2,%3,%4};"
                     :: "r"(bStage + bdoff), "r"(w0), "r"(w1), "r"(w2), "r"(w3)
                     : "memory");
    };

    // ---- ldmatrix offsets (16 warps: wm 0..7 x 64 rows, wn 0..1 x 32 cols) --
    const int wm = wid >> 1;
    const int wn = wid & 1;
    const int lr = lane & 7;
    const int lj = lane >> 3;
    uint32_t aOff[4][4], bOff[4][2];
#pragma unroll
    for (int ks = 0; ks < 4; ks++) {
#pragma unroll
        for (int mf = 0; mf < 4; mf++) {
            int row = wm * 64 + mf * 16 + lr + (lj & 1) * 8;
            int c16 = 2 * ks + (lj >> 1);
            aOff[ks][mf] = (uint32_t)(row * 128 + ((c16 ^ lr) << 4));
        }
#pragma unroll
        for (int nh = 0; nh < 2; nh++) {
            int nrow = wn * 32 + nh * 16 + lr + (lj >> 1) * 8;
            int c16  = 2 * ks + (lj & 1);
            bOff[ks][nh] = (uint32_t)(nrow * 128 + ((c16 ^ lr) << 4));
        }
    }

    float acc[4][4][4];
#pragma unroll
    for (int a = 0; a < 4; a++)
#pragma unroll
        for (int b = 0; b < 4; b++)
#pragma unroll
            for (int q = 0; q < 4; q++) acc[a][b][q] = 0.0f;

    // ---- prologue: fill stages 0,1 with chunks 0,1 ----
    bLDG(0); bSTS(sB0);
    bLDG(1); bSTS(sB0 + BSZ);
    fillA(0, sA0);
    fillA(1, sA0 + ASZ);

    // ---- main loop: one sync per chunk; refill LDGs first, STS after MMA ----
    int s = 0;
    for (int i = 0; i < NCH; i++) {
        const int t = (s + 2 >= 3) ? s - 1 : s + 2;   // (i+2)%3
        if (i < NCH - 1) asm volatile("cp.async.wait_group 1;" ::: "memory");
        else             asm volatile("cp.async.wait_group 0;" ::: "memory");
        __syncthreads();

        const bool refill = (i + 2 < NCH);
        if (refill) {
            bLDG(i + 2);                       // latency covered by MMA below
            fillA(i + 2, sA0 + t * ASZ);
        }

        uint32_t aBase = sA0 + s * ASZ;
        uint32_t bBase = sB0 + s * BSZ;
#pragma unroll
        for (int ks = 0; ks < 4; ks++) {
            uint32_t a_frag[4][4];
            uint32_t b_frag[4][2];
#pragma unroll
            for (int mf = 0; mf < 4; mf++)
                ldsm_x4(a_frag[mf], aBase + aOff[ks][mf]);
#pragma unroll
            for (int nh = 0; nh < 2; nh++) {
                uint32_t r[4];
                ldsm_x4(r, bBase + bOff[ks][nh]);
                b_frag[2 * nh][0]     = r[0];
                b_frag[2 * nh][1]     = r[1];
                b_frag[2 * nh + 1][0] = r[2];
                b_frag[2 * nh + 1][1] = r[3];
            }
#pragma unroll
            for (int mf = 0; mf < 4; mf++)
#pragma unroll
                for (int nf = 0; nf < 4; nf++)
                    mma16816(acc[mf][nf], a_frag[mf], b_frag[nf]);
        }

        if (refill) bSTS(sB0 + t * BSZ);       // visible after next top sync

        if (++s == 3) s = 0;
    }

    // ---- epilogue: plain float2 stores into the partial plane ----
    float* plane = g_part + (size_t)kq * PLANE;
    const int lq = lane >> 2;
    const int lp = lane & 3;
#pragma unroll
    for (int mf = 0; mf < 4; mf++) {
        int grow = wm * 64 + mf * 16 + lq;
#pragma unroll
        for (int nf = 0; nf < 4; nf++) {
            int gcol = n0 + wn * 32 + nf * 8 + 2 * lp;
            float* p = plane + (size_t)grow * OUT_ + gcol;
            float2 v0, v1;
            v0.x = acc[mf][nf][0];
            v0.y = acc[mf][nf][1];
            v1.x = acc[mf][nf][2];
            v1.y = acc[mf][nf][3];
            *reinterpret_cast<float2*>(p)            = v0;
            *reinterpret_cast<float2*>(p + 8 * OUT_) = v1;
        }
    }
}

// ---------------- reduce kernel: out = (sum(partials) + bias) * scale --------
__global__ void reduce_kernel(const float* __restrict__ bias,
                              const float* __restrict__ scale,
                              float* __restrict__ out) {
    const int n4 = (int)(PLANE / 4);
    int stride = gridDim.x * blockDim.x;
    for (int i = blockIdx.x * blockDim.x + threadIdx.x; i < n4; i += stride) {
        size_t e = (size_t)i * 4;
        int col = (int)(e % OUT_);
        float4 p0 = __ldg(reinterpret_cast<const float4*>(g_part + e));
        float4 p1 = __ldg(reinterpret_cast<const float4*>(g_part + PLANE + e));
        float4 p2 = __ldg(reinterpret_cast<const float4*>(g_part + 2 * PLANE + e));
        float4 p3 = __ldg(reinterpret_cast<const float4*>(g_part + 3 * PLANE + e));
        float4 b  = __ldg(reinterpret_cast<const float4*>(bias + col));
        float4 c  = __ldg(reinterpret_cast<const float4*>(scale + col));
        float4 r;
        r.x = (p0.x + p1.x + p2.x + p3.x + b.x) * c.x;
        r.y = (p0.y + p1.y + p2.y + p3.y + b.y) * c.y;
        r.z = (p0.z + p1.z + p2.z + p3.z + b.z) * c.z;
        r.w = (p0.w + p1.w + p2.w + p3.w + b.w) * c.w;
        reinterpret_cast<float4*>(out)[i] = r;
    }
}

// ---------------- launch -----------------------------------------------------
extern "C" void kernel_launch(void* const* d_in, const int* in_sizes, int n_in,
                              void* d_out, int out_size) {
    const float* x      = (const float*)d_in[0];
    const int*   stored = (const int*)d_in[1];
    const int*   sign   = (const int*)d_in[2];
    const float* lmin   = (const float*)d_in[3];
    const float* lmax   = (const float*)d_in[4];
    const float* scale  = (const float*)d_in[5];
    const float* bias   = (const float*)d_in[6];
    float* out = (float*)d_out;

    cudaFuncSetAttribute(fused_kernel, cudaFuncAttributeMaxDynamicSharedMemorySize,
                         (int)SMEM_REQ);

    xconv_kernel<<<512, 256>>>(x);
    fused_kernel<<<NTILES * KSPLIT, 512, SMEM_REQ>>>(stored, sign, lmin, lmax);
    reduce_kernel<<<1024, 256>>>(bias, scale, out);
}